// round 5
// baseline (speedup 1.0000x reference)
#include <cuda_runtime.h>

#define N_ROWS 16384
#define D      2048
#define NUM_LABELS 1024
#define NUM_CAMS   8
#define S (NUM_LABELS * NUM_CAMS)   // 8192 segments
#define MAXC 32                     // max rows per segment cached in smem

// ---- scratch (device globals; no allocation allowed) ----
__device__ int    g_count[S];
__device__ int    g_offset[S];
__device__ int    g_order[N_ROWS];
__device__ int    g_done;
__device__ double g_partial[S];

// ---------------------------------------------------------------------------
// K_PREP: ONE block, 1024 threads. Does everything the old 4 kernels did:
//   - detect int64 vs int32 storage of labels/cam_ids (odd-word probe)
//   - smem histogram of 16384 segment ids into 8192 bins
//   - in-smem exclusive scan (8 entries/thread + Hillis-Steele over totals)
//   - scatter: smem cursor starts at offset, atomicAdd return IS the position
//   - reset g_done for k_main's last-block protocol
// ---------------------------------------------------------------------------
__global__ __launch_bounds__(1024) void k_prep(const int* __restrict__ lab32,
                                               const int* __restrict__ cam32) {
    __shared__ int cnt_s[S];      // histogram -> exclusive offsets -> cursors
    __shared__ int tsum[1024];
    __shared__ int s_any;
    int t = threadIdx.x;

    // zero histogram (each thread owns contiguous [t*8, t*8+8))
#pragma unroll
    for (int j = 0; j < 8; j++) cnt_s[t * 8 + j] = 0;
    if (t == 0) { s_any = 0; g_done = 0; }
    __syncthreads();

    // int64 detection: if arrays are little-endian int64 with values < 2^31,
    // all odd int32 words of cam_ids are zero; if int32, cam values 0..7 make
    // odd positions nonzero with overwhelming probability.
    int probe = 0;
    for (int i = t; i < N_ROWS / 8; i += 1024) probe |= cam32[2 * i + 1];
    if (probe) atomicOr(&s_any, 1);
    __syncthreads();
    int stride = s_any ? 1 : 2;

    // segment ids (16/thread, coalesced) + smem histogram
    int seg[16];
#pragma unroll
    for (int j = 0; j < 16; j++) {
        int i = t + j * 1024;
        int lab = lab32[i * stride];
        int cam = cam32[i * stride];
        seg[j] = lab * NUM_CAMS + cam;
        atomicAdd(&cnt_s[seg[j]], 1);
    }
    __syncthreads();

    // exclusive scan: local 8-entry serial prefix + Hillis-Steele over totals
    int c[8];
    int run = 0;
#pragma unroll
    for (int j = 0; j < 8; j++) { c[j] = cnt_s[t * 8 + j]; run += c[j]; }
    tsum[t] = run;
    __syncthreads();
    for (int off = 1; off < 1024; off <<= 1) {
        int v = (t >= off) ? tsum[t - off] : 0;
        __syncthreads();
        tsum[t] += v;
        __syncthreads();
    }
    int ex = (t == 0) ? 0 : tsum[t - 1];
#pragma unroll
    for (int j = 0; j < 8; j++) {
        int s = t * 8 + j;
        g_count[s]  = c[j];
        g_offset[s] = ex;
        cnt_s[s]    = ex;   // cursor initialized to exclusive offset
        ex += c[j];
    }
    __syncthreads();

    // scatter: atomicAdd on the offset-initialized cursor returns the slot
#pragma unroll
    for (int j = 0; j < 16; j++) {
        int i = t + j * 1024;
        int pos = atomicAdd(&cnt_s[seg[j]], 1);
        g_order[pos] = i;
    }
}

__device__ __forceinline__ float sl1(float d) {
    float ad = fabsf(d);
    return ad < 1.0f ? 0.5f * d * d : ad - 0.5f;
}

// ---------------------------------------------------------------------------
// K_MAIN: one CTA per segment. Pass 1 sums rows -> mean; pass 2 SmoothL1 vs
// mean (pass-2 row reads hit L1: same CTA just read them). cnt<=1 segments
// contribute exactly zero (mean == the row). The LAST block to finish runs
// the deterministic final reduction over g_partial and writes the scalar.
// ---------------------------------------------------------------------------
__global__ __launch_bounds__(256) void k_main(const float* __restrict__ feats,
                                              float* __restrict__ out) {
    __shared__ int   rows_s[MAXC];
    __shared__ float wsum[8];
    __shared__ bool  s_last;
    int s = blockIdx.x;
    int t = threadIdx.x;
    int cnt = g_count[s];

    if (cnt >= 2) {
        int base = g_offset[s];
        int ccap = min(cnt, MAXC);
        if (t < ccap) rows_s[t] = g_order[base + t];
        __syncthreads();

        // thread t owns cols [4t,4t+4) and [1024+4t,1024+4t+4)
        float4 s0 = make_float4(0.f, 0.f, 0.f, 0.f);
        float4 s1 = make_float4(0.f, 0.f, 0.f, 0.f);
        for (int r = 0; r < cnt; r++) {
            int row = (r < MAXC) ? rows_s[r] : g_order[base + r];
            const float4* p = (const float4*)(feats + (size_t)row * D);
            float4 a = p[t];
            float4 b = p[t + 256];
            s0.x += a.x; s0.y += a.y; s0.z += a.z; s0.w += a.w;
            s1.x += b.x; s1.y += b.y; s1.z += b.z; s1.w += b.w;
        }
        float inv = 1.0f / (float)cnt;
        float4 m0 = make_float4(s0.x * inv, s0.y * inv, s0.z * inv, s0.w * inv);
        float4 m1 = make_float4(s1.x * inv, s1.y * inv, s1.z * inv, s1.w * inv);

        float acc = 0.f;
        for (int r = 0; r < cnt; r++) {
            int row = (r < MAXC) ? rows_s[r] : g_order[base + r];
            const float4* p = (const float4*)(feats + (size_t)row * D);
            float4 a = p[t];          // L1 hit
            float4 b = p[t + 256];
            acc += sl1(a.x - m0.x) + sl1(a.y - m0.y) + sl1(a.z - m0.z) + sl1(a.w - m0.w);
            acc += sl1(b.x - m1.x) + sl1(b.y - m1.y) + sl1(b.z - m1.z) + sl1(b.w - m1.w);
        }
#pragma unroll
        for (int off = 16; off; off >>= 1)
            acc += __shfl_down_sync(0xffffffffu, acc, off);
        if ((t & 31) == 0) wsum[t >> 5] = acc;
        __syncthreads();
        if (t == 0) {
            float tot = 0.f;
#pragma unroll
            for (int w = 0; w < 8; w++) tot += wsum[w];
            g_partial[s] = (double)tot;
        }
    } else {
        if (t == 0) g_partial[s] = 0.0;
    }

    // last-block-does-final-reduction protocol (deterministic reduction tree)
    if (t == 0) {
        __threadfence();
        int d = atomicAdd(&g_done, 1);
        s_last = (d == S - 1);
    }
    __syncthreads();
    if (!s_last) return;
    __threadfence();

    __shared__ double red[256];
    double local = 0.0;
    for (int i = t; i < S; i += 256) local += g_partial[i];
    red[t] = local;
    __syncthreads();
    for (int off = 128; off; off >>= 1) {
        if (t < off) red[t] += red[t + off];
        __syncthreads();
    }
    if (t == 0) out[0] = (float)(red[0] / ((double)N_ROWS * (double)D));
}

extern "C" void kernel_launch(void* const* d_in, const int* in_sizes, int n_in,
                              void* d_out, int out_size) {
    const float* feats = (const float*)d_in[0];
    const int*   lab32 = (const int*)d_in[1];
    const int*   cam32 = (const int*)d_in[2];
    float* out = (float*)d_out;

    k_prep<<<1, 1024>>>(lab32, cam32);
    k_main<<<S, 256>>>(feats, out);
}

// round 6
// speedup vs baseline: 1.3840x; 1.3840x over previous
#include <cuda_runtime.h>

#define N_ROWS 16384
#define D      2048
#define NUM_LABELS 1024
#define NUM_CAMS   8
#define S (NUM_LABELS * NUM_CAMS)   // 8192 segments
#define SLOT_CAP 24                 // P(Poisson(2) > 24) ~ 1e-16; fallback exists
#define KREG 8                      // register-resident single-pass path bound
#define SEG_PER_CTA 8
#define NBLK (S / SEG_PER_CTA)      // 1024 main CTAs
#define TPB 512                     // thread t owns cols [4t, 4t+4)

// ---- scratch (device globals; invariant: g_count/g_done zero at entry,
// ---- restored by k_main's last block after every run) ----
__device__ int    g_count[S];
__device__ int    g_slots[S * SLOT_CAP];
__device__ int    g_seg[N_ROWS];
__device__ int    g_done;
__device__ double g_partial[NBLK];

// ---------------------------------------------------------------------------
// K_BUILD: 32 blocks x 512 threads, one row per thread.
//  - per-block int64/int32 layout probe (odd int32 words of cam_ids are all
//    zero iff int64; probing words 1..1023 is in-bounds under both layouts)
//  - seg id, g_seg store, and direct slot insertion via atomicAdd position
// ---------------------------------------------------------------------------
__global__ __launch_bounds__(TPB) void k_build(const int* __restrict__ lab32,
                                               const int* __restrict__ cam32) {
    __shared__ int s_any;
    int t = threadIdx.x;
    if (t == 0) s_any = 0;
    __syncthreads();
    int probe = cam32[2 * t + 1];          // safe under int32 and int64 layouts
#pragma unroll
    for (int o = 16; o; o >>= 1) probe |= __shfl_xor_sync(0xffffffffu, probe, o);
    if ((t & 31) == 0 && probe) atomicOr(&s_any, 1);
    __syncthreads();
    int stride = s_any ? 1 : 2;            // int32 : int64

    int i = blockIdx.x * TPB + t;
    int seg = lab32[i * stride] * NUM_CAMS + cam32[i * stride];
    g_seg[i] = seg;
    int pos = atomicAdd(&g_count[seg], 1);
    if (pos < SLOT_CAP) g_slots[seg * SLOT_CAP + pos] = i;
    // rows beyond SLOT_CAP remain discoverable via g_seg (ultra-rare fallback)
}

__device__ __forceinline__ float sl1(float d) {
    float ad = fabsf(d);
    return ad < 1.0f ? 0.5f * d * d : ad - 0.5f;
}
__device__ __forceinline__ float sl1_4(float4 a, float4 m) {
    return sl1(a.x - m.x) + sl1(a.y - m.y) + sl1(a.z - m.z) + sl1(a.w - m.w);
}

// ---------------------------------------------------------------------------
// K_MAIN: 1024 CTAs x 512 threads; each CTA handles 8 segments.
// cnt<=1  : zero loss, skip.
// cnt<=8  : single-pass — 8 unconditional unrolled LDG.128 into registers
//           (k>=cnt duplicates row 0 -> L1 hit), mean + SmoothL1 in registers.
// cnt<=24 : two-pass via slots (pass 2 hits L1).
// cnt>24  : correctness-only g_seg scan.
// Last block reduces g_partial, writes out, and resets g_count/g_done.
// ---------------------------------------------------------------------------
__global__ __launch_bounds__(TPB) void k_main(const float* __restrict__ feats,
                                              float* __restrict__ out) {
    __shared__ int   s_cnt[SEG_PER_CTA];
    __shared__ int   s_slot[SEG_PER_CTA * SLOT_CAP];
    __shared__ float wsum[TPB / 32];
    __shared__ bool  s_last;
    int t = threadIdx.x;
    int s0 = blockIdx.x * SEG_PER_CTA;

    if (t < SEG_PER_CTA) s_cnt[t] = g_count[s0 + t];
    if (t < SEG_PER_CTA * SLOT_CAP) {
        int si = t / SLOT_CAP, j = t % SLOT_CAP;
        s_slot[t] = g_slots[(s0 + si) * SLOT_CAP + j];  // stale entries unused
    }
    __syncthreads();

    float facc = 0.f;
    for (int si = 0; si < SEG_PER_CTA; si++) {
        int cnt = s_cnt[si];
        if (cnt < 2) continue;               // mean == row -> zero contribution
        const int* sl = s_slot + si * SLOT_CAP;

        if (cnt <= KREG) {
            // ---- register-resident single pass, 8 loads in flight ----
            float4 v[KREG];
            float4 sum = make_float4(0.f, 0.f, 0.f, 0.f);
#pragma unroll
            for (int k = 0; k < KREG; k++) {
                int r = sl[(k < cnt) ? k : 0];
                v[k] = __ldg((const float4*)(feats + (size_t)r * D) + t);
            }
#pragma unroll
            for (int k = 0; k < KREG; k++) {
                if (k >= cnt) v[k] = make_float4(0.f, 0.f, 0.f, 0.f);
                sum.x += v[k].x; sum.y += v[k].y; sum.z += v[k].z; sum.w += v[k].w;
            }
            float inv = 1.0f / (float)cnt;
            float4 m = make_float4(sum.x * inv, sum.y * inv, sum.z * inv, sum.w * inv);
#pragma unroll
            for (int k = 0; k < KREG; k++)
                if (k < cnt) facc += sl1_4(v[k], m);
        } else if (cnt <= SLOT_CAP) {
            // ---- two-pass via slots; pass 2 hits L1 ----
            float4 sum = make_float4(0.f, 0.f, 0.f, 0.f);
            for (int k = 0; k < cnt; k++) {
                float4 a = __ldg((const float4*)(feats + (size_t)sl[k] * D) + t);
                sum.x += a.x; sum.y += a.y; sum.z += a.z; sum.w += a.w;
            }
            float inv = 1.0f / (float)cnt;
            float4 m = make_float4(sum.x * inv, sum.y * inv, sum.z * inv, sum.w * inv);
            for (int k = 0; k < cnt; k++) {
                float4 a = __ldg((const float4*)(feats + (size_t)sl[k] * D) + t);
                facc += sl1_4(a, m);
            }
        } else {
            // ---- ultra-rare correctness fallback: scan g_seg ----
            int seg = s0 + si;
            float4 sum = make_float4(0.f, 0.f, 0.f, 0.f);
            for (int r = 0; r < N_ROWS; r++) {
                if (g_seg[r] == seg) {
                    float4 a = __ldg((const float4*)(feats + (size_t)r * D) + t);
                    sum.x += a.x; sum.y += a.y; sum.z += a.z; sum.w += a.w;
                }
            }
            float inv = 1.0f / (float)cnt;
            float4 m = make_float4(sum.x * inv, sum.y * inv, sum.z * inv, sum.w * inv);
            for (int r = 0; r < N_ROWS; r++) {
                if (g_seg[r] == seg) {
                    float4 a = __ldg((const float4*)(feats + (size_t)r * D) + t);
                    facc += sl1_4(a, m);
                }
            }
        }
    }

    // block reduction: 16 warps -> double partial per CTA
#pragma unroll
    for (int o = 16; o; o >>= 1)
        facc += __shfl_down_sync(0xffffffffu, facc, o);
    if ((t & 31) == 0) wsum[t >> 5] = facc;
    __syncthreads();
    if (t == 0) {
        float tot = 0.f;
#pragma unroll
        for (int w = 0; w < TPB / 32; w++) tot += wsum[w];
        g_partial[blockIdx.x] = (double)tot;
    }

    // last-block final reduction + scratch cleanup for the next graph replay
    if (t == 0) {
        __threadfence();
        s_last = (atomicAdd(&g_done, 1) == NBLK - 1);
    }
    __syncthreads();
    if (!s_last) return;
    __threadfence();

    __shared__ double red[TPB];
    double local = 0.0;
    for (int i = t; i < NBLK; i += TPB) local += g_partial[i];
    red[t] = local;
    __syncthreads();
    for (int o = TPB / 2; o; o >>= 1) {
        if (t < o) red[t] += red[t + o];
        __syncthreads();
    }
    if (t == 0) {
        out[0] = (float)(red[0] / ((double)N_ROWS * (double)D));
        g_done = 0;
    }
    for (int i = t; i < S; i += TPB) g_count[i] = 0;   // restore invariant
}

extern "C" void kernel_launch(void* const* d_in, const int* in_sizes, int n_in,
                              void* d_out, int out_size) {
    const float* feats = (const float*)d_in[0];
    const int*   lab32 = (const int*)d_in[1];
    const int*   cam32 = (const int*)d_in[2];
    float* out = (float*)d_out;

    k_build<<<N_ROWS / TPB, TPB>>>(lab32, cam32);   // 32 blocks
    k_main <<<NBLK, TPB>>>(feats, out);             // 1024 blocks
}

// round 7
// speedup vs baseline: 1.6954x; 1.2250x over previous
#include <cuda_runtime.h>

#define N_ROWS 16384
#define D      2048
#define NUM_LABELS 1024
#define NUM_CAMS   8
#define S (NUM_LABELS * NUM_CAMS)   // 8192 segments
#define SLOT_CAP 24                 // P(Poisson(2) > 24) ~ 1e-16; fallback exists
#define KREG 4                      // register single-pass bound (87% of cnt>=2)
#define SEG_PER_CTA 4
#define NBLK (S / SEG_PER_CTA)      // 2048 main CTAs
#define TPB 512                     // thread t owns cols [4t, 4t+4)

// ---- scratch (device globals; invariant: g_count/g_done zero at entry,
// ---- restored by k_main's last block after every run) ----
__device__ int    g_count[S];
__device__ int    g_slots[S * SLOT_CAP];
__device__ int    g_seg[N_ROWS];
__device__ int    g_done;
__device__ double g_partial[NBLK];

// ---------------------------------------------------------------------------
// K_BUILD: 32 blocks x 512 threads, one row per thread.
//  - int64/int32 layout probe (odd int32 words of cam_ids all zero iff int64)
//  - seg id, g_seg store, direct slot insertion via atomicAdd position
// ---------------------------------------------------------------------------
__global__ __launch_bounds__(TPB) void k_build(const int* __restrict__ lab32,
                                               const int* __restrict__ cam32) {
    __shared__ int s_any;
    int t = threadIdx.x;
    if (t == 0) s_any = 0;
    __syncthreads();
    int probe = cam32[2 * t + 1];          // in-bounds under both layouts
#pragma unroll
    for (int o = 16; o; o >>= 1) probe |= __shfl_xor_sync(0xffffffffu, probe, o);
    if ((t & 31) == 0 && probe) atomicOr(&s_any, 1);
    __syncthreads();
    int stride = s_any ? 1 : 2;            // int32 : int64

    int i = blockIdx.x * TPB + t;
    int seg = lab32[i * stride] * NUM_CAMS + cam32[i * stride];
    g_seg[i] = seg;
    int pos = atomicAdd(&g_count[seg], 1);
    if (pos < SLOT_CAP) g_slots[seg * SLOT_CAP + pos] = i;
}

__device__ __forceinline__ float sl1(float d) {
    float ad = fabsf(d);
    return ad < 1.0f ? 0.5f * d * d : ad - 0.5f;
}
__device__ __forceinline__ float sl1_4(float4 a, float4 m) {
    return sl1(a.x - m.x) + sl1(a.y - m.y) + sl1(a.z - m.z) + sl1(a.w - m.w);
}
__device__ __forceinline__ void acc4(float4& s, float4 a) {
    s.x += a.x; s.y += a.y; s.z += a.z; s.w += a.w;
}

// ---------------------------------------------------------------------------
// K_MAIN: 2048 CTAs x 512 threads, 4 segments each, 3 CTAs/SM forced.
// cnt dispatch:  <2 skip | ==2 exact+symmetry | 3..4 reg single-pass |
//                5..24 two-pass via slots (pass2 L1 hit) | >24 g_seg scan.
// Last block reduces g_partial, writes out, resets g_count/g_done.
// ---------------------------------------------------------------------------
__global__ __launch_bounds__(TPB, 3) void k_main(const float* __restrict__ feats,
                                                 float* __restrict__ out) {
    __shared__ int   s_cnt[SEG_PER_CTA];
    __shared__ int   s_slot[SEG_PER_CTA * SLOT_CAP];
    __shared__ float wsum[TPB / 32];
    __shared__ bool  s_last;
    int t = threadIdx.x;
    int s0 = blockIdx.x * SEG_PER_CTA;

    if (t < SEG_PER_CTA) s_cnt[t] = g_count[s0 + t];
    if (t < SEG_PER_CTA * SLOT_CAP) {
        int si = t / SLOT_CAP, j = t % SLOT_CAP;
        s_slot[t] = g_slots[(s0 + si) * SLOT_CAP + j];
    }
    __syncthreads();

    float facc = 0.f;
#pragma unroll
    for (int si = 0; si < SEG_PER_CTA; si++) {
        int cnt = s_cnt[si];
        if (cnt < 2) continue;               // mean == row -> zero contribution
        const int* sl = s_slot + si * SLOT_CAP;

        if (cnt == 2) {
            // exact 2 loads; d0 = -(d1) => per-element losses are equal
            float4 v0 = __ldg((const float4*)(feats + (size_t)sl[0] * D) + t);
            float4 v1 = __ldg((const float4*)(feats + (size_t)sl[1] * D) + t);
            float4 m = make_float4(0.5f * (v0.x + v1.x), 0.5f * (v0.y + v1.y),
                                   0.5f * (v0.z + v1.z), 0.5f * (v0.w + v1.w));
            facc += 2.0f * sl1_4(v0, m);
        } else if (cnt <= KREG) {
            // 4 loads in flight (k>=cnt dups sl[0] -> L1 hit), reg single-pass
            float4 v[KREG];
            float4 sum = make_float4(0.f, 0.f, 0.f, 0.f);
#pragma unroll
            for (int k = 0; k < KREG; k++) {
                int r = sl[(k < cnt) ? k : 0];
                v[k] = __ldg((const float4*)(feats + (size_t)r * D) + t);
            }
#pragma unroll
            for (int k = 0; k < KREG; k++) {
                if (k >= cnt) v[k] = make_float4(0.f, 0.f, 0.f, 0.f);
                acc4(sum, v[k]);
            }
            float inv = 1.0f / (float)cnt;
            float4 m = make_float4(sum.x * inv, sum.y * inv, sum.z * inv, sum.w * inv);
#pragma unroll
            for (int k = 0; k < KREG; k++)
                if (k < cnt) facc += sl1_4(v[k], m);
        } else if (cnt <= SLOT_CAP) {
            // two-pass via slots; pass 2 hits L1
            float4 sum = make_float4(0.f, 0.f, 0.f, 0.f);
            for (int k = 0; k < cnt; k++)
                acc4(sum, __ldg((const float4*)(feats + (size_t)sl[k] * D) + t));
            float inv = 1.0f / (float)cnt;
            float4 m = make_float4(sum.x * inv, sum.y * inv, sum.z * inv, sum.w * inv);
            for (int k = 0; k < cnt; k++)
                facc += sl1_4(__ldg((const float4*)(feats + (size_t)sl[k] * D) + t), m);
        } else {
            // ultra-rare correctness fallback: scan g_seg
            int seg = s0 + si;
            float4 sum = make_float4(0.f, 0.f, 0.f, 0.f);
            for (int r = 0; r < N_ROWS; r++)
                if (g_seg[r] == seg)
                    acc4(sum, __ldg((const float4*)(feats + (size_t)r * D) + t));
            float inv = 1.0f / (float)cnt;
            float4 m = make_float4(sum.x * inv, sum.y * inv, sum.z * inv, sum.w * inv);
            for (int r = 0; r < N_ROWS; r++)
                if (g_seg[r] == seg)
                    facc += sl1_4(__ldg((const float4*)(feats + (size_t)r * D) + t), m);
        }
    }

    // block reduction: 16 warps -> double partial per CTA
#pragma unroll
    for (int o = 16; o; o >>= 1)
        facc += __shfl_down_sync(0xffffffffu, facc, o);
    if ((t & 31) == 0) wsum[t >> 5] = facc;
    __syncthreads();
    if (t == 0) {
        float tot = 0.f;
#pragma unroll
        for (int w = 0; w < TPB / 32; w++) tot += wsum[w];
        g_partial[blockIdx.x] = (double)tot;
    }

    // last-block final reduction + scratch cleanup for next graph replay
    if (t == 0) {
        __threadfence();
        s_last = (atomicAdd(&g_done, 1) == NBLK - 1);
    }
    __syncthreads();
    if (!s_last) return;
    __threadfence();

    __shared__ double red[TPB];
    double local = 0.0;
    for (int i = t; i < NBLK; i += TPB) local += g_partial[i];
    red[t] = local;
    __syncthreads();
    for (int o = TPB / 2; o; o >>= 1) {
        if (t < o) red[t] += red[t + o];
        __syncthreads();
    }
    if (t == 0) {
        out[0] = (float)(red[0] / ((double)N_ROWS * (double)D));
        g_done = 0;
    }
    for (int i = t; i < S; i += TPB) g_count[i] = 0;   // restore invariant
}

extern "C" void kernel_launch(void* const* d_in, const int* in_sizes, int n_in,
                              void* d_out, int out_size) {
    const float* feats = (const float*)d_in[0];
    const int*   lab32 = (const int*)d_in[1];
    const int*   cam32 = (const int*)d_in[2];
    float* out = (float*)d_out;

    k_build<<<N_ROWS / TPB, TPB>>>(lab32, cam32);   // 32 blocks
    k_main <<<NBLK, TPB>>>(feats, out);             // 2048 blocks
}

// round 8
// speedup vs baseline: 1.8921x; 1.1160x over previous
#include <cuda_runtime.h>

#define N_ROWS 16384
#define D      2048
#define D4     (D / 4)              // 512 float4 per row
#define NUM_LABELS 1024
#define NUM_CAMS   8
#define S (NUM_LABELS * NUM_CAMS)   // 8192 segments
#define SLOT_CAP 24                 // P(Poisson(2) > 24) ~ 1e-16; fallback exists
#define CHUNKS 16                   // 16 chunks x 32 lanes x float4 = 2048 cols
#define TPB 256
#define NBLK_MAIN 1184              // 148 SMs x 8 CTAs (grid-stride anyway)
#define NWARPS (NBLK_MAIN * (TPB / 32))

// ---- scratch (device globals; invariant: g_count/g_ndesc/g_nbig/g_done zero
// ---- at entry, restored by k_main's last block after every run) ----
__device__ int    g_count[S];
__device__ int    g_slots[S * SLOT_CAP];
__device__ int    g_seg[N_ROWS];
__device__ int4   g_desc[S];        // packed cnt-2..4 segments, rows pre-padded
__device__ int    g_big[S];         // seg ids with cnt >= 5
__device__ int    g_ndesc;
__device__ int    g_nbig;
__device__ int    g_done;
__device__ double g_partial[NBLK_MAIN];

// ---------------------------------------------------------------------------
// K_BUILD: 32 blocks x 512 threads, one row per thread.
// int64/int32 layout probe (odd int32 words of cam_ids all zero iff int64),
// seg id, g_seg store, direct slot insertion via atomicAdd position.
// ---------------------------------------------------------------------------
__global__ __launch_bounds__(512) void k_build(const int* __restrict__ lab32,
                                               const int* __restrict__ cam32) {
    __shared__ int s_any;
    int t = threadIdx.x;
    if (t == 0) s_any = 0;
    __syncthreads();
    int probe = cam32[2 * t + 1];          // in-bounds under both layouts
#pragma unroll
    for (int o = 16; o; o >>= 1) probe |= __shfl_xor_sync(0xffffffffu, probe, o);
    if ((t & 31) == 0 && probe) atomicOr(&s_any, 1);
    __syncthreads();
    int stride = s_any ? 1 : 2;            // int32 : int64

    int i = blockIdx.x * 512 + t;
    int seg = lab32[i * stride] * NUM_CAMS + cam32[i * stride];
    g_seg[i] = seg;
    int pos = atomicAdd(&g_count[seg], 1);
    if (pos < SLOT_CAP) g_slots[seg * SLOT_CAP + pos] = i;
}

// ---------------------------------------------------------------------------
// K_PACK: one thread per segment. cnt 2..4 -> padded int4 descriptor
// (dup r0 fills unused rows; dup loads are same-warp L1 hits in k_main).
// cnt >= 5 -> big list. cnt <= 1 -> dropped (zero loss contribution).
// ---------------------------------------------------------------------------
__global__ __launch_bounds__(512) void k_pack() {
    int s = blockIdx.x * 512 + threadIdx.x;
    int cnt = g_count[s];
    if (cnt < 2) return;
    if (cnt <= 4) {
        const int* sl = g_slots + s * SLOT_CAP;
        int r0 = sl[0];
        int4 d;
        d.x = r0;
        d.y = sl[1];
        d.z = (cnt > 2) ? sl[2] : r0;
        int r3 = (cnt > 3) ? sl[3] : r0;
        d.w = r3 | (cnt << 16);
        g_desc[atomicAdd(&g_ndesc, 1)] = d;
    } else {
        g_big[atomicAdd(&g_nbig, 1)] = s;
    }
}

__device__ __forceinline__ float sl1(float d) {
    float ad = fabsf(d);
    return ad < 1.0f ? 0.5f * d * d : ad - 0.5f;
}
__device__ __forceinline__ float sl1_4(float4 a, float4 m) {
    return sl1(a.x - m.x) + sl1(a.y - m.y) + sl1(a.z - m.z) + sl1(a.w - m.w);
}
__device__ __forceinline__ void acc4(float4& s, float4 a) {
    s.x += a.x; s.y += a.y; s.z += a.z; s.w += a.w;
}

// ---------------------------------------------------------------------------
// K_MAIN: flat warp-item stream, no CTA-level coupling in the main loops.
// Item = (segment, 128-col chunk). Phase B (big segs, two-pass via slots,
// pass 2 = L1 hit) first, then phase A (descriptor segs: 4 unconditional
// LDG.128, predicated math, next descriptor software-prefetched).
// Last block reduces g_partial, writes out, resets scratch invariants.
// ---------------------------------------------------------------------------
__global__ __launch_bounds__(TPB) void k_main(const float* __restrict__ feats,
                                              float* __restrict__ out) {
    __shared__ float wsum[TPB / 32];
    __shared__ bool  s_last;
    int t = threadIdx.x;
    int lane = t & 31;
    int gw = blockIdx.x * (TPB / 32) + (t >> 5);
    const float4* __restrict__ F = (const float4*)feats;
    int ndesc = g_ndesc;
    int nbig  = g_nbig;
    float facc = 0.f;

    // ---------------- phase B: big segments (cnt >= 5), ~430 expected ------
    int nitemsB = nbig * CHUNKS;
    for (int u = gw; u < nitemsB; u += NWARPS) {
        int seg = g_big[u >> 4];
        int col = (u & 15) * 32 + lane;
        int cnt = g_count[seg];
        if (cnt <= SLOT_CAP) {
            const int* sl = g_slots + seg * SLOT_CAP;
            float4 sum = make_float4(0.f, 0.f, 0.f, 0.f);
            for (int k = 0; k < cnt; k++)
                acc4(sum, __ldg(F + (size_t)sl[k] * D4 + col));
            float inv = 1.0f / (float)cnt;
            float4 m = make_float4(sum.x * inv, sum.y * inv, sum.z * inv, sum.w * inv);
            for (int k = 0; k < cnt; k++)
                facc += sl1_4(__ldg(F + (size_t)sl[k] * D4 + col), m);
        } else {
            // ultra-rare correctness fallback: scan g_seg
            float4 sum = make_float4(0.f, 0.f, 0.f, 0.f);
            for (int r = 0; r < N_ROWS; r++)
                if (g_seg[r] == seg) acc4(sum, __ldg(F + (size_t)r * D4 + col));
            float inv = 1.0f / (float)cnt;
            float4 m = make_float4(sum.x * inv, sum.y * inv, sum.z * inv, sum.w * inv);
            for (int r = 0; r < N_ROWS; r++)
                if (g_seg[r] == seg) facc += sl1_4(__ldg(F + (size_t)r * D4 + col), m);
        }
    }

    // ---------------- phase A: descriptor segments (cnt 2..4), hot path ----
    int nitemsA = ndesc * CHUNKS;
    int u = gw;
    int4 dd = (u < nitemsA) ? g_desc[u >> 4] : make_int4(0, 0, 0, 0);
    while (u < nitemsA) {
        int un = u + NWARPS;
        int4 ddn = (un < nitemsA) ? g_desc[un >> 4] : dd;   // prefetch next

        int cnt = dd.w >> 16;
        int r3  = dd.w & 0xFFFF;
        int col = (u & 15) * 32 + lane;
        float4 v0 = __ldg(F + (size_t)dd.x * D4 + col);
        float4 v1 = __ldg(F + (size_t)dd.y * D4 + col);
        float4 v2 = __ldg(F + (size_t)dd.z * D4 + col);     // L1 hit if padded
        float4 v3 = __ldg(F + (size_t)r3   * D4 + col);     // L1 hit if padded

        float4 sum = make_float4(v0.x + v1.x, v0.y + v1.y, v0.z + v1.z, v0.w + v1.w);
        if (cnt > 2) acc4(sum, v2);
        if (cnt > 3) acc4(sum, v3);
        float inv = 1.0f / (float)cnt;
        float4 m = make_float4(sum.x * inv, sum.y * inv, sum.z * inv, sum.w * inv);

        facc += sl1_4(v0, m) + sl1_4(v1, m);
        if (cnt > 2) facc += sl1_4(v2, m);
        if (cnt > 3) facc += sl1_4(v3, m);

        dd = ddn;
        u = un;
    }

    // ---------------- reduction: warp -> CTA -> g_partial ------------------
#pragma unroll
    for (int o = 16; o; o >>= 1)
        facc += __shfl_down_sync(0xffffffffu, facc, o);
    if (lane == 0) wsum[t >> 5] = facc;
    __syncthreads();
    if (t == 0) {
        float tot = 0.f;
#pragma unroll
        for (int w = 0; w < TPB / 32; w++) tot += wsum[w];
        g_partial[blockIdx.x] = (double)tot;
    }

    // last-block final reduction + scratch cleanup for next graph replay
    if (t == 0) {
        __threadfence();
        s_last = (atomicAdd(&g_done, 1) == NBLK_MAIN - 1);
    }
    __syncthreads();
    if (!s_last) return;
    __threadfence();

    __shared__ double red[TPB];
    double local = 0.0;
    for (int i = t; i < NBLK_MAIN; i += TPB) local += g_partial[i];
    red[t] = local;
    __syncthreads();
    for (int o = TPB / 2; o; o >>= 1) {
        if (t < o) red[t] += red[t + o];
        __syncthreads();
    }
    if (t == 0) {
        out[0] = (float)(red[0] / ((double)N_ROWS * (double)D));
        g_done = 0;
        g_ndesc = 0;
        g_nbig = 0;
    }
    for (int i = t; i < S; i += TPB) g_count[i] = 0;   // restore invariant
}

extern "C" void kernel_launch(void* const* d_in, const int* in_sizes, int n_in,
                              void* d_out, int out_size) {
    const float* feats = (const float*)d_in[0];
    const int*   lab32 = (const int*)d_in[1];
    const int*   cam32 = (const int*)d_in[2];
    float* out = (float*)d_out;

    k_build<<<N_ROWS / 512, 512>>>(lab32, cam32);   // 32 blocks
    k_pack <<<S / 512, 512>>>();                    // 16 blocks
    k_main <<<NBLK_MAIN, TPB>>>(feats, out);        // 1184 blocks
}

// round 9
// speedup vs baseline: 2.0067x; 1.0606x over previous
#include <cuda_runtime.h>

#define N_ROWS 16384
#define D      2048
#define D4     (D / 4)              // 512 float4 per row
#define NUM_LABELS 1024
#define NUM_CAMS   8
#define S (NUM_LABELS * NUM_CAMS)   // 8192 segments
#define SLOT_CAP 24                 // P(Poisson(2) > 24) ~ 1e-16; fallback exists
#define TPB 256
#define NBLK_MAIN 1184
#define NWARPS (NBLK_MAIN * (TPB / 32))

// ---- scratch (device globals; invariant: counters zero at entry, restored
// ---- by k_main's last block after every run) ----
__device__ int    g_count[S];
__device__ int    g_slots[S * SLOT_CAP];
__device__ int    g_seg[N_ROWS];
__device__ int2   g_d2[S];          // exact cnt==2 descriptors
__device__ int4   g_d3[S];          // exact cnt==3 (w unused)
__device__ int4   g_d4[S];          // exact cnt==4
__device__ int    g_big[S];         // seg ids with cnt >= 5
__device__ int    g_n2, g_n3, g_n4, g_nbig;
__device__ int    g_done;
__device__ double g_partial[NBLK_MAIN];

// ---------------------------------------------------------------------------
// K_BUILD: 128 blocks x 128 threads (4x the SM coverage of R7) — this kernel
// is a single dependent chain per thread (LDG -> ATOMG -> STG); spread it.
// int64/int32 layout probe: odd int32 words of cam_ids all zero iff int64.
// ---------------------------------------------------------------------------
__global__ __launch_bounds__(128) void k_build(const int* __restrict__ lab32,
                                               const int* __restrict__ cam32) {
    __shared__ int s_any;
    int t = threadIdx.x;
    if (t == 0) s_any = 0;
    __syncthreads();
    int probe = cam32[2 * t + 1];          // idx <= 255: in-bounds both layouts
#pragma unroll
    for (int o = 16; o; o >>= 1) probe |= __shfl_xor_sync(0xffffffffu, probe, o);
    if ((t & 31) == 0 && probe) atomicOr(&s_any, 1);
    __syncthreads();
    int stride = s_any ? 1 : 2;            // int32 : int64

    int i = blockIdx.x * 128 + t;
    int seg = lab32[i * stride] * NUM_CAMS + cam32[i * stride];
    g_seg[i] = seg;
    int pos = atomicAdd(&g_count[seg], 1);
    if (pos < SLOT_CAP) g_slots[seg * SLOT_CAP + pos] = i;
}

// ---------------------------------------------------------------------------
// K_PACK: one thread per segment -> exact per-count lists (no padding).
// cnt <= 1 dropped (zero loss contribution).
// ---------------------------------------------------------------------------
__global__ __launch_bounds__(512) void k_pack() {
    int s = blockIdx.x * 512 + threadIdx.x;
    int cnt = g_count[s];
    if (cnt < 2) return;
    const int* sl = g_slots + s * SLOT_CAP;
    if (cnt == 2) {
        g_d2[atomicAdd(&g_n2, 1)] = make_int2(sl[0], sl[1]);
    } else if (cnt == 3) {
        g_d3[atomicAdd(&g_n3, 1)] = make_int4(sl[0], sl[1], sl[2], 0);
    } else if (cnt == 4) {
        g_d4[atomicAdd(&g_n4, 1)] = make_int4(sl[0], sl[1], sl[2], sl[3]);
    } else {
        g_big[atomicAdd(&g_nbig, 1)] = s;
    }
}

__device__ __forceinline__ float sl1(float d) {
    float ad = fabsf(d);
    return ad < 1.0f ? 0.5f * d * d : ad - 0.5f;
}
__device__ __forceinline__ float sl1_4(float4 a, float4 m) {
    return sl1(a.x - m.x) + sl1(a.y - m.y) + sl1(a.z - m.z) + sl1(a.w - m.w);
}
__device__ __forceinline__ void acc4(float4& s, float4 a) {
    s.x += a.x; s.y += a.y; s.z += a.z; s.w += a.w;
}
// cnt==2 symmetry: per-element loss x2 of half-difference
__device__ __forceinline__ float sl1_4_half(float4 a, float4 b) {
    return 2.0f * (sl1(0.5f * (a.x - b.x)) + sl1(0.5f * (a.y - b.y)) +
                   sl1(0.5f * (a.z - b.z)) + sl1(0.5f * (a.w - b.w)));
}

// ---------------------------------------------------------------------------
// K_MAIN: flat warp-item stream over four exact phases (big, d4, d3, d2).
// d4/d3: item = 256 cols (2 float4/thread/row) -> 8/6 exact LDG.128 in flight.
// d2:    item = 512 cols (4 float4/thread/row) -> 8 exact LDG.128 in flight,
//        symmetry halves the arithmetic. Descriptors software-prefetched.
// Last block reduces g_partial, writes out, resets scratch invariants.
// ---------------------------------------------------------------------------
__global__ __launch_bounds__(TPB) void k_main(const float* __restrict__ feats,
                                              float* __restrict__ out) {
    __shared__ float wsum[TPB / 32];
    __shared__ bool  s_last;
    int t = threadIdx.x;
    int lane = t & 31;
    int gw = blockIdx.x * (TPB / 32) + (t >> 5);
    const float4* __restrict__ F = (const float4*)feats;
    float facc = 0.f;

    // ---------------- phase BIG: cnt >= 5, two-pass via slots (pass2 L1) ---
    {
        int nitems = g_nbig * 8;                       // 256-col chunks
        for (int u = gw; u < nitems; u += NWARPS) {
            int seg = g_big[u >> 3];
            int col = (u & 7) * 64 + lane;
            int cnt = g_count[seg];
            if (cnt <= SLOT_CAP) {
                const int* sl = g_slots + seg * SLOT_CAP;
                float4 s0 = make_float4(0.f, 0.f, 0.f, 0.f);
                float4 s1 = make_float4(0.f, 0.f, 0.f, 0.f);
                for (int k = 0; k < cnt; k++) {
                    const float4* p = F + (size_t)sl[k] * D4 + col;
                    acc4(s0, __ldg(p)); acc4(s1, __ldg(p + 32));
                }
                float inv = 1.0f / (float)cnt;
                float4 m0 = make_float4(s0.x*inv, s0.y*inv, s0.z*inv, s0.w*inv);
                float4 m1 = make_float4(s1.x*inv, s1.y*inv, s1.z*inv, s1.w*inv);
                for (int k = 0; k < cnt; k++) {
                    const float4* p = F + (size_t)sl[k] * D4 + col;
                    facc += sl1_4(__ldg(p), m0) + sl1_4(__ldg(p + 32), m1);
                }
            } else {                                   // ~1e-16 fallback
                float4 s0 = make_float4(0.f, 0.f, 0.f, 0.f);
                float4 s1 = make_float4(0.f, 0.f, 0.f, 0.f);
                for (int r = 0; r < N_ROWS; r++)
                    if (g_seg[r] == seg) {
                        const float4* p = F + (size_t)r * D4 + col;
                        acc4(s0, __ldg(p)); acc4(s1, __ldg(p + 32));
                    }
                float inv = 1.0f / (float)cnt;
                float4 m0 = make_float4(s0.x*inv, s0.y*inv, s0.z*inv, s0.w*inv);
                float4 m1 = make_float4(s1.x*inv, s1.y*inv, s1.z*inv, s1.w*inv);
                for (int r = 0; r < N_ROWS; r++)
                    if (g_seg[r] == seg) {
                        const float4* p = F + (size_t)r * D4 + col;
                        facc += sl1_4(__ldg(p), m0) + sl1_4(__ldg(p + 32), m1);
                    }
            }
        }
    }

    // ---------------- phase D4: cnt == 4, 8 exact loads ---------------------
    {
        int nitems = g_n4 * 8;
        int u = gw;
        int4 dd = (u < nitems) ? g_d4[u >> 3] : make_int4(0, 0, 0, 0);
        while (u < nitems) {
            int un = u + NWARPS;
            int4 ddn = (un < nitems) ? g_d4[un >> 3] : dd;
            int col = (u & 7) * 64 + lane;
            const float4* p0 = F + (size_t)dd.x * D4 + col;
            const float4* p1 = F + (size_t)dd.y * D4 + col;
            const float4* p2 = F + (size_t)dd.z * D4 + col;
            const float4* p3 = F + (size_t)dd.w * D4 + col;
            float4 a0 = __ldg(p0), b0 = __ldg(p0 + 32);
            float4 a1 = __ldg(p1), b1 = __ldg(p1 + 32);
            float4 a2 = __ldg(p2), b2 = __ldg(p2 + 32);
            float4 a3 = __ldg(p3), b3 = __ldg(p3 + 32);
            float4 m0 = make_float4(0.25f*(a0.x+a1.x+a2.x+a3.x), 0.25f*(a0.y+a1.y+a2.y+a3.y),
                                    0.25f*(a0.z+a1.z+a2.z+a3.z), 0.25f*(a0.w+a1.w+a2.w+a3.w));
            float4 m1 = make_float4(0.25f*(b0.x+b1.x+b2.x+b3.x), 0.25f*(b0.y+b1.y+b2.y+b3.y),
                                    0.25f*(b0.z+b1.z+b2.z+b3.z), 0.25f*(b0.w+b1.w+b2.w+b3.w));
            facc += sl1_4(a0, m0) + sl1_4(a1, m0) + sl1_4(a2, m0) + sl1_4(a3, m0);
            facc += sl1_4(b0, m1) + sl1_4(b1, m1) + sl1_4(b2, m1) + sl1_4(b3, m1);
            dd = ddn; u = un;
        }
    }

    // ---------------- phase D3: cnt == 3, 6 exact loads ---------------------
    {
        int nitems = g_n3 * 8;
        int u = gw;
        int4 dd = (u < nitems) ? g_d3[u >> 3] : make_int4(0, 0, 0, 0);
        const float third = 1.0f / 3.0f;
        while (u < nitems) {
            int un = u + NWARPS;
            int4 ddn = (un < nitems) ? g_d3[un >> 3] : dd;
            int col = (u & 7) * 64 + lane;
            const float4* p0 = F + (size_t)dd.x * D4 + col;
            const float4* p1 = F + (size_t)dd.y * D4 + col;
            const float4* p2 = F + (size_t)dd.z * D4 + col;
            float4 a0 = __ldg(p0), b0 = __ldg(p0 + 32);
            float4 a1 = __ldg(p1), b1 = __ldg(p1 + 32);
            float4 a2 = __ldg(p2), b2 = __ldg(p2 + 32);
            float4 m0 = make_float4(third*(a0.x+a1.x+a2.x), third*(a0.y+a1.y+a2.y),
                                    third*(a0.z+a1.z+a2.z), third*(a0.w+a1.w+a2.w));
            float4 m1 = make_float4(third*(b0.x+b1.x+b2.x), third*(b0.y+b1.y+b2.y),
                                    third*(b0.z+b1.z+b2.z), third*(b0.w+b1.w+b2.w));
            facc += sl1_4(a0, m0) + sl1_4(a1, m0) + sl1_4(a2, m0);
            facc += sl1_4(b0, m1) + sl1_4(b1, m1) + sl1_4(b2, m1);
            dd = ddn; u = un;
        }
    }

    // ---------------- phase D2: cnt == 2, 512-col items, symmetry ----------
    {
        int nitems = g_n2 * 4;                         // 4 chunks of 512 cols
        int u = gw;
        int2 dd = (u < nitems) ? g_d2[u >> 2] : make_int2(0, 0);
        while (u < nitems) {
            int un = u + NWARPS;
            int2 ddn = (un < nitems) ? g_d2[un >> 2] : dd;
            int col = (u & 3) * 128 + lane;
            const float4* p0 = F + (size_t)dd.x * D4 + col;
            const float4* p1 = F + (size_t)dd.y * D4 + col;
            float4 a0 = __ldg(p0),      a1 = __ldg(p0 + 32),
                   a2 = __ldg(p0 + 64), a3 = __ldg(p0 + 96);
            float4 c0 = __ldg(p1),      c1 = __ldg(p1 + 32),
                   c2 = __ldg(p1 + 64), c3 = __ldg(p1 + 96);
            facc += sl1_4_half(a0, c0) + sl1_4_half(a1, c1) +
                    sl1_4_half(a2, c2) + sl1_4_half(a3, c3);
            dd = ddn; u = un;
        }
    }

    // ---------------- reduction: warp -> CTA -> g_partial ------------------
#pragma unroll
    for (int o = 16; o; o >>= 1)
        facc += __shfl_down_sync(0xffffffffu, facc, o);
    if (lane == 0) wsum[t >> 5] = facc;
    __syncthreads();
    if (t == 0) {
        float tot = 0.f;
#pragma unroll
        for (int w = 0; w < TPB / 32; w++) tot += wsum[w];
        g_partial[blockIdx.x] = (double)tot;
    }

    // last-block final reduction + scratch cleanup for next graph replay
    if (t == 0) {
        __threadfence();
        s_last = (atomicAdd(&g_done, 1) == NBLK_MAIN - 1);
    }
    __syncthreads();
    if (!s_last) return;
    __threadfence();

    __shared__ double red[TPB];
    double local = 0.0;
    for (int i = t; i < NBLK_MAIN; i += TPB) local += g_partial[i];
    red[t] = local;
    __syncthreads();
    for (int o = TPB / 2; o; o >>= 1) {
        if (t < o) red[t] += red[t + o];
        __syncthreads();
    }
    if (t == 0) {
        out[0] = (float)(red[0] / ((double)N_ROWS * (double)D));
        g_done = 0; g_n2 = 0; g_n3 = 0; g_n4 = 0; g_nbig = 0;
    }
    for (int i = t; i < S; i += TPB) g_count[i] = 0;   // restore invariant
}

extern "C" void kernel_launch(void* const* d_in, const int* in_sizes, int n_in,
                              void* d_out, int out_size) {
    const float* feats = (const float*)d_in[0];
    const int*   lab32 = (const int*)d_in[1];
    const int*   cam32 = (const int*)d_in[2];
    float* out = (float*)d_out;

    k_build<<<N_ROWS / 128, 128>>>(lab32, cam32);   // 128 blocks
    k_pack <<<S / 512, 512>>>();                    // 16 blocks
    k_main <<<NBLK_MAIN, TPB>>>(feats, out);        // 1184 blocks
}